// round 15
// baseline (speedup 1.0000x reference)
#include <cuda_runtime.h>
#include <cuda_fp16.h>
#include <math.h>
#include <stdint.h>

// Problem constants
#define BB 2
#define TT 2048
#define DD 1024
#define HH 16
#define HD 64
#define MROWS (BB*TT)        // 4096
#define LOG2E 1.44269504088896340736f

// Scratch (device globals; allocation is forbidden). All fp16.
__device__ __half g_Q[BB*HH*TT*HD];   // [B,H,T,hd], scaled by 0.125*log2e
__device__ __half g_K[BB*HH*TT*HD];
__device__ __half g_V[BB*HH*TT*HD];
__device__ __half g_O[MROWS*DD];      // [B*T, D]
__device__ __half g_Xh[3*MROWS*DD];   // fp16 query/key/value
__device__ __half g_Wh[4*DD*DD];      // fp16 Wq/Wk/Wv/Wo

// ---------------------------------------------------------------------------
// helpers
// ---------------------------------------------------------------------------
__device__ __forceinline__ uint32_t smem_u32(const void* p) {
    uint32_t a;
    asm("{ .reg .u64 t; cvta.to.shared.u64 t, %1; cvt.u32.u64 %0, t; }"
        : "=r"(a) : "l"(p));
    return a;
}
// pack two floats into half2 (lo = first arg)
__device__ __forceinline__ uint32_t h2pack(float lo, float hi) {
    uint32_t r;
    asm("cvt.rn.f16x2.f32 %0, %1, %2;" : "=r"(r) : "f"(hi), "f"(lo));
    return r;
}
__device__ __forceinline__ float ex2(float x) {
    float y;
    asm("ex2.approx.f32 %0, %1;" : "=f"(y) : "f"(x));
    return y;
}
// packed half2 exp2
__device__ __forceinline__ uint32_t ex2_h2(uint32_t x) {
    uint32_t y;
    asm("ex2.approx.f16x2 %0, %1;" : "=r"(y) : "r"(x));
    return y;
}
__device__ __forceinline__ void cp16(uint32_t dst, const void* src) {
    asm volatile("cp.async.cg.shared.global [%0], [%1], 16;"
                 :: "r"(dst), "l"(src));
}
#define CP_COMMIT() asm volatile("cp.async.commit_group;" ::: "memory")
#define CP_WAIT(N)  asm volatile("cp.async.wait_group %0;" :: "n"(N) : "memory")

__device__ __forceinline__ void ldm_x4(uint32_t r[4], uint32_t addr) {
    asm volatile("ldmatrix.sync.aligned.m8n8.x4.shared.b16 {%0,%1,%2,%3}, [%4];"
                 : "=r"(r[0]), "=r"(r[1]), "=r"(r[2]), "=r"(r[3]) : "r"(addr));
}
__device__ __forceinline__ void ldm_x4t(uint32_t r[4], uint32_t addr) {
    asm volatile("ldmatrix.sync.aligned.m8n8.x4.trans.shared.b16 {%0,%1,%2,%3}, [%4];"
                 : "=r"(r[0]), "=r"(r[1]), "=r"(r[2]), "=r"(r[3]) : "r"(addr));
}
// D += A(16x16) * B(16x8), fp16 in, f32 accum
__device__ __forceinline__ void mma_f16(float c[4], const uint32_t a[4],
                                        uint32_t b0, uint32_t b1) {
    asm volatile(
        "mma.sync.aligned.m16n8k16.row.col.f32.f16.f16.f32 "
        "{%0,%1,%2,%3},{%4,%5,%6,%7},{%8,%9},{%0,%1,%2,%3};\n"
        : "+f"(c[0]), "+f"(c[1]), "+f"(c[2]), "+f"(c[3])
        : "r"(a[0]), "r"(a[1]), "r"(a[2]), "r"(a[3]), "r"(b0), "r"(b1));
}

// ---------------------------------------------------------------------------
// Pre-pass: convert inputs and weights to fp16 (single kernel).
// ---------------------------------------------------------------------------
#define XPER (MROWS*DD/8)      // 524288 pairs per X tensor
#define WPER (DD*DD/8)         // 131072 pairs per W tensor
#define XPAIRS (3*XPER)
#define WPAIRS (4*WPER)

__global__ __launch_bounds__(256)
void round_all(const float4* __restrict__ q, const float4* __restrict__ k,
               const float4* __restrict__ v,
               const float4* __restrict__ w0, const float4* __restrict__ w1,
               const float4* __restrict__ w2, const float4* __restrict__ w3)
{
    int e = blockIdx.x * 256 + threadIdx.x;
    const float4* src;
    uint4* dst;
    int off;
    if (e < XPAIRS) {
        int z = e / XPER;
        off = e - z * XPER;
        src = (z == 0) ? q : (z == 1) ? k : v;
        dst = (uint4*)(g_Xh + (size_t)z * MROWS * DD);
    } else {
        int e2 = e - XPAIRS;
        int z = e2 / WPER;
        off = e2 - z * WPER;
        src = (z == 0) ? w0 : (z == 1) ? w1 : (z == 2) ? w2 : w3;
        dst = (uint4*)(g_Wh + (size_t)z * DD * DD);
    }
    float4 a = src[2 * off], b = src[2 * off + 1];
    uint4 o;
    o.x = h2pack(a.x, a.y); o.y = h2pack(a.z, a.w);
    o.z = h2pack(b.x, b.y); o.w = h2pack(b.z, b.w);
    dst[off] = o;
}

// ---------------------------------------------------------------------------
// fp16 GEMM core: 128x128 tile, BK=64, 3-stage cp.async, ldmatrix frags.
// cp.async issue split: A-half after kk=0's mmas, B-half+commit after kk=1's.
// ---------------------------------------------------------------------------
#define LDA 72
#define LDW 136
#define ASTG (128*LDA)             // 9216 halves
#define BSTG (64*LDW)              // 8704 halves
#define STG  (ASTG+BSTG)           // 17920 halves
#define GEMM_SMEM_BYTES (3*STG*2)  // 107520

__device__ __forceinline__ void gemm128x128(
    const __half* __restrict__ X, const __half* __restrict__ W,
    int m0, int n0, __half* sm, float acc[2][8][4])
{
    const int tid  = threadIdx.x;
    const int lane = tid & 31;
    const int w    = tid >> 5;
    const int wm   = w >> 1;
    const int wn   = w & 1;

    const uint32_t sbase = smem_u32(sm);

#pragma unroll
    for (int mt = 0; mt < 2; mt++)
#pragma unroll
        for (int nt = 0; nt < 8; nt++)
#pragma unroll
            for (int i = 0; i < 4; i++) acc[mt][nt][i] = 0.0f;

    auto ISSUE_A = [&](int s) {
        const int k0 = s * 64;
        const uint32_t Ab = sbase + (uint32_t)((s % 3) * STG) * 2;
#pragma unroll
        for (int j = 0; j < 4; j++) {
            const int f = tid + j * 256;
            const int ra = f >> 3, ca = f & 7;
            cp16(Ab + (uint32_t)(ra * LDA + ca * 8) * 2,
                 X + (size_t)(m0 + ra) * DD + k0 + ca * 8);
        }
    };
    auto ISSUE_B = [&](int s) {
        const int k0 = s * 64;
        const uint32_t Bb = sbase + (uint32_t)((s % 3) * STG) * 2 + ASTG * 2;
#pragma unroll
        for (int j = 0; j < 4; j++) {
            const int f = tid + j * 256;
            const int rb = f >> 4, cb = f & 15;
            cp16(Bb + (uint32_t)(rb * LDW + cb * 8) * 2,
                 W + (size_t)(k0 + rb) * DD + n0 + cb * 8);
        }
    };

    ISSUE_A(0); ISSUE_B(0); CP_COMMIT();
    ISSUE_A(1); ISSUE_B(1); CP_COMMIT();

    const int lrow = lane & 15;
    const int lcol = (lane >> 4) << 3;

#pragma unroll 1
    for (int s = 0; s < 16; s++) {
        CP_WAIT(1);
        __syncthreads();

        const uint32_t Ab = sbase + (uint32_t)((s % 3) * STG) * 2;
        const uint32_t Bb = Ab + ASTG * 2;

#pragma unroll
        for (int kk = 0; kk < 4; kk++) {
            uint32_t a[2][4];
#pragma unroll
            for (int mt = 0; mt < 2; mt++) {
                const int r = wm * 32 + mt * 16;
                ldm_x4(a[mt], Ab + (uint32_t)((r + lrow) * LDA + kk * 16 + lcol) * 2);
            }
            uint32_t bb[4][4];
#pragma unroll
            for (int np = 0; np < 4; np++) {
                const int col = wn * 64 + np * 16 + lcol;
                ldm_x4t(bb[np], Bb + (uint32_t)((kk * 16 + lrow) * LDW + col) * 2);
            }
#pragma unroll
            for (int nt = 0; nt < 8; nt++) {
                const int np = nt >> 1, o = (nt & 1) * 2;
                mma_f16(acc[0][nt], a[0], bb[np][o], bb[np][o + 1]);
                mma_f16(acc[1][nt], a[1], bb[np][o], bb[np][o + 1]);
            }
            if (kk == 0) {
                if (s + 2 < 16) ISSUE_A(s + 2);
            } else if (kk == 1) {
                if (s + 2 < 16) ISSUE_B(s + 2);
                CP_COMMIT();
            }
        }
    }
}

// ---------------------------------------------------------------------------
// QKV projection: grid (32, 8, 3), block 256. Outputs fp16 (Q pre-scaled).
// ---------------------------------------------------------------------------
__global__ __launch_bounds__(256, 2)
void qkv_kernel(const float* __restrict__ bq, const float* __restrict__ bk,
                const float* __restrict__ bv)
{
    extern __shared__ __half smh[];
    const int z = blockIdx.z;
    const __half* X   = g_Xh + (size_t)z * MROWS * DD;
    const __half* W   = g_Wh + (size_t)z * DD * DD;
    const float* bias = (z == 0) ? bq : (z == 1) ? bk : bv;
    __half* Out       = (z == 0) ? g_Q : (z == 1) ? g_K : g_V;
    const float scale = (z == 0) ? 0.125f * LOG2E : 1.0f;

    const int m0 = blockIdx.x * 128;
    const int n0 = blockIdx.y * 128;

    float acc[2][8][4];
    gemm128x128(X, W, m0, n0, smh, acc);

    const int lane = threadIdx.x & 31;
    const int w    = threadIdx.x >> 5;
    const int wm   = w >> 1, wn = w & 1;
    const int gr   = lane >> 2, gq = lane & 3;

#pragma unroll
    for (int nt = 0; nt < 8; nt++) {
        int col = n0 + wn * 64 + nt * 8 + gq * 2;
        float b0 = __ldg(bias + col);
        float b1 = __ldg(bias + col + 1);
        int h = col >> 6, d = col & 63;
#pragma unroll
        for (int mt = 0; mt < 2; mt++) {
#pragma unroll
            for (int half = 0; half < 2; half++) {
                int row = m0 + wm * 32 + mt * 16 + gr + half * 8;
                int bi = row >> 11, t = row & (TT - 1);
                uint32_t val = h2pack((acc[mt][nt][half * 2 + 0] + b0) * scale,
                                      (acc[mt][nt][half * 2 + 1] + b1) * scale);
                *(uint32_t*)(Out + ((((size_t)(bi * HH + h)) * TT + t) << 6) + d) = val;
            }
        }
    }
}

// ---------------------------------------------------------------------------
// Output projection: out = g_O @ Wo + bo (final, fp32 out)
// ---------------------------------------------------------------------------
__global__ __launch_bounds__(256, 2)
void out_kernel(const float* __restrict__ bo, float* __restrict__ out)
{
    extern __shared__ __half smh[];
    const int m0 = blockIdx.x * 128;
    const int n0 = blockIdx.y * 128;

    float acc[2][8][4];
    gemm128x128(g_O, g_Wh + (size_t)3 * DD * DD, m0, n0, smh, acc);

    const int lane = threadIdx.x & 31;
    const int w    = threadIdx.x >> 5;
    const int wm   = w >> 1, wn = w & 1;
    const int gr   = lane >> 2, gq = lane & 3;

#pragma unroll
    for (int nt = 0; nt < 8; nt++) {
        int col = n0 + wn * 64 + nt * 8 + gq * 2;
        float b0 = __ldg(bo + col);
        float b1 = __ldg(bo + col + 1);
#pragma unroll
        for (int mt = 0; mt < 2; mt++) {
#pragma unroll
            for (int half = 0; half < 2; half++) {
                int row = m0 + wm * 32 + mt * 16 + gr + half * 8;
                float2 val;
                val.x = acc[mt][nt][half * 2 + 0] + b0;
                val.y = acc[mt][nt][half * 2 + 1] + b1;
                *(float2*)(out + (size_t)row * DD + col) = val;
            }
        }
    }
}

// ---------------------------------------------------------------------------
// fp16 flash attention, 128 q-rows per CTA (halves K/V tile traffic for the
// heavy full-band heads). grid (T/128=16, 16, 2), block 256 (8 warps).
// f16x2-packed exp, ones-column l, 3-stage KV ring, diagonal-outward order,
// vote-skipped rescale, linear-bias fast path for off-diagonal tiles.
// ---------------------------------------------------------------------------
#define LDK 72
#define LDV 72
#define KVH (64*LDK + 64*LDV)          // 9216 halves per buffer
#define ALIBI_MARGIN 28.0f
#define ATTN_SMEM_BYTES (3*KVH*2)      // 55296
#define ONESH2 0x3C003C00u             // half2(1.0, 1.0)

// Diagonal-outward order over [lo, hi] containing qc, each tile exactly once.
__device__ __forceinline__ int tile_at(int it, int qc, int lo, int hi) {
    const int left  = qc - lo;
    const int right = hi - qc;
    const int m = (left < right) ? left : right;
    if (it <= 2 * m) {
        const int d = (it + 1) >> 1;
        return (it & 1) ? (qc - d) : (qc + d);
    }
    const int rem = it - 2 * m;
    return (left > right) ? (qc - m - rem) : (qc + m + rem);
}

__global__ __launch_bounds__(256, 2)
void attn_kernel()
{
    extern __shared__ __half smh[];

    const int qt = blockIdx.x;            // 128-row q tile
    const int h  = HH - 1 - blockIdx.y;   // heavy heads first
    const int b  = blockIdx.z;

    const int tid  = threadIdx.x;
    const int lane = tid & 31;
    const int w    = tid >> 5;            // 0..7
    const int gr   = lane >> 2;
    const int gq   = lane & 3;

    const float slope    = exp2f(-0.5f * (float)(h + 1));
    const float slope_l2 = slope * LOG2E;
    const int q0 = qt * 128;
    const int qc = q0 >> 6;               // left diagonal k-tile (64-col units)

    const int band  = (int)(ALIBI_MARGIN / slope);
    const int kt_lo = max(0, (q0 - band) >> 6);
    const int kt_hi = min(TT / 64 - 1, (q0 + 127 + band) >> 6);
    const int n_tiles = kt_hi - kt_lo + 1;

    const __half* Qb = g_Q + (((size_t)(b * HH + h)) * TT + q0 + w * 16) * HD;
    const __half* Kb = g_K + (((size_t)(b * HH + h)) * TT) * HD;
    const __half* Vb = g_V + (((size_t)(b * HH + h)) * TT) * HD;

    const uint32_t sbase = smem_u32(smh);

    auto ISSUE_K = [&](int kt, int buf) {
        const uint32_t Kd = sbase + (uint32_t)(buf * KVH) * 2;
        const __half* Kg = Kb + (size_t)kt * 64 * HD;
#pragma unroll
        for (int j = 0; j < 2; j++) {
            const int f = tid + j * 256;
            const int r = f >> 3, c = f & 7;
            cp16(Kd + (uint32_t)(r * LDK + c * 8) * 2, Kg + r * HD + c * 8);
        }
    };
    auto ISSUE_V = [&](int kt, int buf) {
        const uint32_t Vd = sbase + (uint32_t)(buf * KVH + 64 * LDK) * 2;
        const __half* Vg = Vb + (size_t)kt * 64 * HD;
#pragma unroll
        for (int j = 0; j < 2; j++) {
            const int f = tid + j * 256;
            const int r = f >> 3, c = f & 7;
            cp16(Vd + (uint32_t)(r * LDV + c * 8) * 2, Vg + r * HD + c * 8);
        }
    };

    // Q fragments (fp16, pre-scaled by 0.125*log2e), loaded once from gmem
    uint32_t qf[4][4];
#pragma unroll
    for (int kk = 0; kk < 4; kk++) {
        qf[kk][0] = *(const uint32_t*)(Qb + (gr)     * HD + kk * 16 + gq * 2);
        qf[kk][1] = *(const uint32_t*)(Qb + (gr + 8) * HD + kk * 16 + gq * 2);
        qf[kk][2] = *(const uint32_t*)(Qb + (gr)     * HD + kk * 16 + gq * 2 + 8);
        qf[kk][3] = *(const uint32_t*)(Qb + (gr + 8) * HD + kk * 16 + gq * 2 + 8);
    }

    // oacc[0..7] = O tiles; oacc[8] = l accumulator (P @ ones column)
    float oacc[9][4];
#pragma unroll
    for (int nt = 0; nt < 9; nt++)
#pragma unroll
        for (int i = 0; i < 4; i++) oacc[nt][i] = 0.0f;

    float m_lo = -INFINITY, m_hi = -INFINITY;

    const int qrow_lo = q0 + w * 16 + gr;
    const int qrow_hi = qrow_lo + 8;
    const float qlo_f = (float)qrow_lo;
    const float qhi_f = (float)qrow_hi;

    const int l15 = lane & 15;
    const int l7  = lane & 7;
    const int hi16 = (lane >> 4) << 3;
    const int mid8 = ((lane >> 3) & 1) << 3;

    {
        const int t0 = tile_at(0, qc, kt_lo, kt_hi);
        ISSUE_K(t0, 0); ISSUE_V(t0, 0); CP_COMMIT();
        if (n_tiles > 1) {
            const int t1 = tile_at(1, qc, kt_lo, kt_hi);
            ISSUE_K(t1, 1); ISSUE_V(t1, 1);
        }
        CP_COMMIT();
    }

#pragma unroll 1
    for (int it = 0; it < n_tiles; it++) {
        const int kt = tile_at(it, qc, kt_lo, kt_hi);
        CP_WAIT(1);
        __syncthreads();

        const uint32_t Ksmb = sbase + (uint32_t)((it % 3) * KVH) * 2;
        const uint32_t Vsmb = Ksmb + (uint32_t)(64 * LDK) * 2;
        const int nextbuf = (it + 2) % 3;
        const bool havenext = (it + 2 < n_tiles);
        const int nextkt = havenext ? tile_at(it + 2, qc, kt_lo, kt_hi) : 0;

        // ---- S = Q @ K^T (log2 domain) ----
        float sacc[8][4];
#pragma unroll
        for (int nt = 0; nt < 8; nt++)
            sacc[nt][0] = sacc[nt][1] = sacc[nt][2] = sacc[nt][3] = 0.0f;

#pragma unroll
        for (int kk = 0; kk < 4; kk++) {
            uint32_t kb[4][4];
#pragma unroll
            for (int p = 0; p < 4; p++) {
                const int row = p * 16 + hi16 + l7;
                const int col = kk * 16 + mid8;
                ldm_x4(kb[p], Ksmb + (uint32_t)(row * LDK + col) * 2);
            }
#pragma unroll
            for (int nt = 0; nt < 8; nt++) {
                const int p = nt >> 1, o = (nt & 1) * 2;
                mma_f16(sacc[nt], qf[kk], kb[p][o], kb[p][o + 1]);
            }
            if (kk == 0) {
                if (havenext) ISSUE_K(nextkt, nextbuf);
            } else if (kk == 1) {
                if (havenext) ISSUE_V(nextkt, nextbuf);
                CP_COMMIT();
            }
        }

        // ---- ALiBi bias + row max ----
        // Diagonal tiles (kt>>1 == qt): fabs path. Otherwise linear fast path.
        const bool diag = ((kt >> 1) == qt);
        const float c  = diag ? 0.0f : ((kt < 2 * qt) ? slope_l2 : -slope_l2);
        const float rowc_lo = -c * qlo_f;
        const float rowc_hi = -c * qhi_f;

        float mx_lo = -INFINITY, mx_hi = -INFINITY;
        if (diag) {
            const int jb = kt * 64 + gq * 2;
#pragma unroll
            for (int nt = 0; nt < 8; nt++) {
                float j0 = (float)(jb + nt * 8);
                float j1 = j0 + 1.0f;
                sacc[nt][0] -= slope_l2 * fabsf(qlo_f - j0);
                sacc[nt][1] -= slope_l2 * fabsf(qlo_f - j1);
                sacc[nt][2] -= slope_l2 * fabsf(qhi_f - j0);
                sacc[nt][3] -= slope_l2 * fabsf(qhi_f - j1);
                mx_lo = fmaxf(mx_lo, fmaxf(sacc[nt][0], sacc[nt][1]));
                mx_hi = fmaxf(mx_hi, fmaxf(sacc[nt][2], sacc[nt][3]));
            }
        } else {
            float cj = c * (float)(kt * 64 + gq * 2);
            const float c8 = c * 8.0f;
#pragma unroll
            for (int nt = 0; nt < 8; nt++) {
                const float cj1 = cj + c;
                sacc[nt][0] += cj;
                sacc[nt][1] += cj1;
                sacc[nt][2] += cj;
                sacc[nt][3] += cj1;
                mx_lo = fmaxf(mx_lo, fmaxf(sacc[nt][0], sacc[nt][1]));
                mx_hi = fmaxf(mx_hi, fmaxf(sacc[nt][2], sacc[nt][3]));
                cj += c8;
            }
            mx_lo += rowc_lo;
            mx_hi += rowc_hi;
        }
        mx_lo = fmaxf(mx_lo, __shfl_xor_sync(0xffffffffu, mx_lo, 1));
        mx_lo = fmaxf(mx_lo, __shfl_xor_sync(0xffffffffu, mx_lo, 2));
        mx_hi = fmaxf(mx_hi, __shfl_xor_sync(0xffffffffu, mx_hi, 1));
        mx_hi = fmaxf(mx_hi, __shfl_xor_sync(0xffffffffu, mx_hi, 2));

        float mn_lo = fmaxf(m_lo, mx_lo);
        float mn_hi = fmaxf(m_hi, mx_hi);
        float corr_lo = ex2(m_lo - mn_lo);
        float corr_hi = ex2(m_hi - mn_hi);
        m_lo = mn_lo; m_hi = mn_hi;

        const float Klo = mn_lo - rowc_lo;
        const float Khi = mn_hi - rowc_hi;

        // ---- exp via packed f16x2 MUFU: deltas -> half2 -> ex2 -> P frags ----
        uint32_t pl[8], ph[8];
#pragma unroll
        for (int nt = 0; nt < 8; nt++) {
            pl[nt] = ex2_h2(h2pack(sacc[nt][0] - Klo, sacc[nt][1] - Klo));
            ph[nt] = ex2_h2(h2pack(sacc[nt][2] - Khi, sacc[nt][3] - Khi));
        }

        // rescale O/l only when some row's max moved (exact skip otherwise)
        const bool need = (corr_lo != 1.0f) || (corr_hi != 1.0f);
        if (__any_sync(0xffffffffu, need)) {
#pragma unroll
            for (int nt = 0; nt < 9; nt++) {
                oacc[nt][0] *= corr_lo;
                oacc[nt][1] *= corr_lo;
                oacc[nt][2] *= corr_hi;
                oacc[nt][3] *= corr_hi;
            }
        }

        // ---- O += P @ V ; l += P @ 1 ----
#pragma unroll
        for (int kk = 0; kk < 4; kk++) {
            uint32_t pa[4];
            pa[0] = pl[2 * kk];
            pa[1] = ph[2 * kk];
            pa[2] = pl[2 * kk + 1];
            pa[3] = ph[2 * kk + 1];
            uint32_t vb[4][4];
#pragma unroll
            for (int np = 0; np < 4; np++) {
                const int row = kk * 16 + l15;
                const int col = np * 16 + hi16;
                ldm_x4t(vb[np], Vsmb + (uint32_t)(row * LDV + col) * 2);
            }
#pragma unroll
            for (int nt = 0; nt < 8; nt++) {
                const int np = nt >> 1, o = (nt & 1) * 2;
                mma_f16(oacc[nt], pa, vb[np][o], vb[np][o + 1]);
            }
            mma_f16(oacc[8], pa, ONESH2, ONESH2);   // row sums of P
        }
    }

    // epilogue: O /= l
    float inv_lo = 1.0f / oacc[8][0];
    float inv_hi = 1.0f / oacc[8][2];
    __half* Ob = g_O + ((size_t)(b * TT + q0 + w * 16)) * DD + h * HD;
#pragma unroll
    for (int nt = 0; nt < 8; nt++) {
        *(uint32_t*)(Ob + (size_t)(gr)     * DD + nt * 8 + gq * 2) =
            h2pack(oacc[nt][0] * inv_lo, oacc[nt][1] * inv_lo);
        *(uint32_t*)(Ob + (size_t)(gr + 8) * DD + nt * 8 + gq * 2) =
            h2pack(oacc[nt][2] * inv_hi, oacc[nt][3] * inv_hi);
    }
}

// ---------------------------------------------------------------------------
extern "C" void kernel_launch(void* const* d_in, const int* in_sizes, int n_in,
                              void* d_out, int out_size)
{
    const float* query = (const float*)d_in[0];
    const float* key_  = (const float*)d_in[1];
    const float* value = (const float*)d_in[2];
    const float* Wq    = (const float*)d_in[3];
    const float* bq    = (const float*)d_in[4];
    const float* Wk    = (const float*)d_in[5];
    const float* bk    = (const float*)d_in[6];
    const float* Wv    = (const float*)d_in[7];
    const float* bv    = (const float*)d_in[8];
    const float* Wo    = (const float*)d_in[9];
    const float* bo    = (const float*)d_in[10];
    float* out = (float*)d_out;

    static int attr_done = 0;
    if (!attr_done) {
        cudaFuncSetAttribute(qkv_kernel, cudaFuncAttributeMaxDynamicSharedMemorySize,
                             GEMM_SMEM_BYTES);
        cudaFuncSetAttribute(out_kernel, cudaFuncAttributeMaxDynamicSharedMemorySize,
                             GEMM_SMEM_BYTES);
        cudaFuncSetAttribute(attn_kernel, cudaFuncAttributeMaxDynamicSharedMemorySize,
                             ATTN_SMEM_BYTES);
        attr_done = 1;
    }

    round_all<<<(XPAIRS + WPAIRS) / 256, 256>>>(
        (const float4*)query, (const float4*)key_, (const float4*)value,
        (const float4*)Wq, (const float4*)Wk, (const float4*)Wv, (const float4*)Wo);

    dim3 gqkv(MROWS / 128, DD / 128, 3);
    qkv_kernel<<<gqkv, 256, GEMM_SMEM_BYTES>>>(bq, bk, bv);

    dim3 gattn(TT / 128, HH, BB);
    attn_kernel<<<gattn, 256, ATTN_SMEM_BYTES>>>();

    dim3 gout(MROWS / 128, DD / 128);
    out_kernel<<<gout, 256, GEMM_SMEM_BYTES>>>(bo, out);
}

// round 16
// speedup vs baseline: 1.0314x; 1.0314x over previous
#include <cuda_runtime.h>
#include <cuda_fp16.h>
#include <math.h>
#include <stdint.h>

// Problem constants
#define BB 2
#define TT 2048
#define DD 1024
#define HH 16
#define HD 64
#define MROWS (BB*TT)        // 4096
#define LOG2E 1.44269504088896340736f

// Scratch (device globals; allocation is forbidden). All fp16.
__device__ __half g_Q[BB*HH*TT*HD];   // [B,H,T,hd], scaled by 0.125*log2e
__device__ __half g_K[BB*HH*TT*HD];
__device__ __half g_V[BB*HH*TT*HD];
__device__ __half g_O[MROWS*DD];      // [B*T, D]
__device__ __half g_Xh[3*MROWS*DD];   // fp16 query/key/value
__device__ __half g_Wh[4*DD*DD];      // fp16 Wq/Wk/Wv/Wo

// ---------------------------------------------------------------------------
// helpers
// ---------------------------------------------------------------------------
__device__ __forceinline__ uint32_t smem_u32(const void* p) {
    uint32_t a;
    asm("{ .reg .u64 t; cvta.to.shared.u64 t, %1; cvt.u32.u64 %0, t; }"
        : "=r"(a) : "l"(p));
    return a;
}
// pack two floats into half2 (lo = first arg)
__device__ __forceinline__ uint32_t h2pack(float lo, float hi) {
    uint32_t r;
    asm("cvt.rn.f16x2.f32 %0, %1, %2;" : "=r"(r) : "f"(hi), "f"(lo));
    return r;
}
__device__ __forceinline__ float ex2(float x) {
    float y;
    asm("ex2.approx.f32 %0, %1;" : "=f"(y) : "f"(x));
    return y;
}
// packed half2 exp2
__device__ __forceinline__ uint32_t ex2_h2(uint32_t x) {
    uint32_t y;
    asm("ex2.approx.f16x2 %0, %1;" : "=r"(y) : "r"(x));
    return y;
}
__device__ __forceinline__ void cp16(uint32_t dst, const void* src) {
    asm volatile("cp.async.cg.shared.global [%0], [%1], 16;"
                 :: "r"(dst), "l"(src));
}
#define CP_COMMIT() asm volatile("cp.async.commit_group;" ::: "memory")
#define CP_WAIT(N)  asm volatile("cp.async.wait_group %0;" :: "n"(N) : "memory")

__device__ __forceinline__ void ldm_x4(uint32_t r[4], uint32_t addr) {
    asm volatile("ldmatrix.sync.aligned.m8n8.x4.shared.b16 {%0,%1,%2,%3}, [%4];"
                 : "=r"(r[0]), "=r"(r[1]), "=r"(r[2]), "=r"(r[3]) : "r"(addr));
}
__device__ __forceinline__ void ldm_x4t(uint32_t r[4], uint32_t addr) {
    asm volatile("ldmatrix.sync.aligned.m8n8.x4.trans.shared.b16 {%0,%1,%2,%3}, [%4];"
                 : "=r"(r[0]), "=r"(r[1]), "=r"(r[2]), "=r"(r[3]) : "r"(addr));
}
// D += A(16x16) * B(16x8), fp16 in, f32 accum
__device__ __forceinline__ void mma_f16(float c[4], const uint32_t a[4],
                                        uint32_t b0, uint32_t b1) {
    asm volatile(
        "mma.sync.aligned.m16n8k16.row.col.f32.f16.f16.f32 "
        "{%0,%1,%2,%3},{%4,%5,%6,%7},{%8,%9},{%0,%1,%2,%3};\n"
        : "+f"(c[0]), "+f"(c[1]), "+f"(c[2]), "+f"(c[3])
        : "r"(a[0]), "r"(a[1]), "r"(a[2]), "r"(a[3]), "r"(b0), "r"(b1));
}

// ---------------------------------------------------------------------------
// Pre-pass: convert inputs and weights to fp16 (single kernel).
// ---------------------------------------------------------------------------
#define XPER (MROWS*DD/8)      // 524288 pairs per X tensor
#define WPER (DD*DD/8)         // 131072 pairs per W tensor
#define XPAIRS (3*XPER)
#define WPAIRS (4*WPER)

__global__ __launch_bounds__(256)
void round_all(const float4* __restrict__ q, const float4* __restrict__ k,
               const float4* __restrict__ v,
               const float4* __restrict__ w0, const float4* __restrict__ w1,
               const float4* __restrict__ w2, const float4* __restrict__ w3)
{
    int e = blockIdx.x * 256 + threadIdx.x;
    const float4* src;
    uint4* dst;
    int off;
    if (e < XPAIRS) {
        int z = e / XPER;
        off = e - z * XPER;
        src = (z == 0) ? q : (z == 1) ? k : v;
        dst = (uint4*)(g_Xh + (size_t)z * MROWS * DD);
    } else {
        int e2 = e - XPAIRS;
        int z = e2 / WPER;
        off = e2 - z * WPER;
        src = (z == 0) ? w0 : (z == 1) ? w1 : (z == 2) ? w2 : w3;
        dst = (uint4*)(g_Wh + (size_t)z * DD * DD);
    }
    float4 a = src[2 * off], b = src[2 * off + 1];
    uint4 o;
    o.x = h2pack(a.x, a.y); o.y = h2pack(a.z, a.w);
    o.z = h2pack(b.x, b.y); o.w = h2pack(b.z, b.w);
    dst[off] = o;
}

// ---------------------------------------------------------------------------
// fp16 GEMM core: 128x128 tile, BK=64, 3-stage cp.async, ldmatrix frags.
// cp.async issue split: A-half after kk=0's mmas, B-half+commit after kk=1's.
// ---------------------------------------------------------------------------
#define LDA 72
#define LDW 136
#define ASTG (128*LDA)             // 9216 halves
#define BSTG (64*LDW)              // 8704 halves
#define STG  (ASTG+BSTG)           // 17920 halves
#define GEMM_SMEM_BYTES (3*STG*2)  // 107520

__device__ __forceinline__ void gemm128x128(
    const __half* __restrict__ X, const __half* __restrict__ W,
    int m0, int n0, __half* sm, float acc[2][8][4])
{
    const int tid  = threadIdx.x;
    const int lane = tid & 31;
    const int w    = tid >> 5;
    const int wm   = w >> 1;
    const int wn   = w & 1;

    const uint32_t sbase = smem_u32(sm);

#pragma unroll
    for (int mt = 0; mt < 2; mt++)
#pragma unroll
        for (int nt = 0; nt < 8; nt++)
#pragma unroll
            for (int i = 0; i < 4; i++) acc[mt][nt][i] = 0.0f;

    auto ISSUE_A = [&](int s) {
        const int k0 = s * 64;
        const uint32_t Ab = sbase + (uint32_t)((s % 3) * STG) * 2;
#pragma unroll
        for (int j = 0; j < 4; j++) {
            const int f = tid + j * 256;
            const int ra = f >> 3, ca = f & 7;
            cp16(Ab + (uint32_t)(ra * LDA + ca * 8) * 2,
                 X + (size_t)(m0 + ra) * DD + k0 + ca * 8);
        }
    };
    auto ISSUE_B = [&](int s) {
        const int k0 = s * 64;
        const uint32_t Bb = sbase + (uint32_t)((s % 3) * STG) * 2 + ASTG * 2;
#pragma unroll
        for (int j = 0; j < 4; j++) {
            const int f = tid + j * 256;
            const int rb = f >> 4, cb = f & 15;
            cp16(Bb + (uint32_t)(rb * LDW + cb * 8) * 2,
                 W + (size_t)(k0 + rb) * DD + n0 + cb * 8);
        }
    };

    ISSUE_A(0); ISSUE_B(0); CP_COMMIT();
    ISSUE_A(1); ISSUE_B(1); CP_COMMIT();

    const int lrow = lane & 15;
    const int lcol = (lane >> 4) << 3;

#pragma unroll 1
    for (int s = 0; s < 16; s++) {
        CP_WAIT(1);
        __syncthreads();

        const uint32_t Ab = sbase + (uint32_t)((s % 3) * STG) * 2;
        const uint32_t Bb = Ab + ASTG * 2;

#pragma unroll
        for (int kk = 0; kk < 4; kk++) {
            uint32_t a[2][4];
#pragma unroll
            for (int mt = 0; mt < 2; mt++) {
                const int r = wm * 32 + mt * 16;
                ldm_x4(a[mt], Ab + (uint32_t)((r + lrow) * LDA + kk * 16 + lcol) * 2);
            }
            uint32_t bb[4][4];
#pragma unroll
            for (int np = 0; np < 4; np++) {
                const int col = wn * 64 + np * 16 + lcol;
                ldm_x4t(bb[np], Bb + (uint32_t)((kk * 16 + lrow) * LDW + col) * 2);
            }
#pragma unroll
            for (int nt = 0; nt < 8; nt++) {
                const int np = nt >> 1, o = (nt & 1) * 2;
                mma_f16(acc[0][nt], a[0], bb[np][o], bb[np][o + 1]);
                mma_f16(acc[1][nt], a[1], bb[np][o], bb[np][o + 1]);
            }
            if (kk == 0) {
                if (s + 2 < 16) ISSUE_A(s + 2);
            } else if (kk == 1) {
                if (s + 2 < 16) ISSUE_B(s + 2);
                CP_COMMIT();
            }
        }
    }
}

// ---------------------------------------------------------------------------
// QKV projection: grid (32, 8, 3), block 256. Outputs fp16 (Q pre-scaled).
// ---------------------------------------------------------------------------
__global__ __launch_bounds__(256, 2)
void qkv_kernel(const float* __restrict__ bq, const float* __restrict__ bk,
                const float* __restrict__ bv)
{
    extern __shared__ __half smh[];
    const int z = blockIdx.z;
    const __half* X   = g_Xh + (size_t)z * MROWS * DD;
    const __half* W   = g_Wh + (size_t)z * DD * DD;
    const float* bias = (z == 0) ? bq : (z == 1) ? bk : bv;
    __half* Out       = (z == 0) ? g_Q : (z == 1) ? g_K : g_V;
    const float scale = (z == 0) ? 0.125f * LOG2E : 1.0f;

    const int m0 = blockIdx.x * 128;
    const int n0 = blockIdx.y * 128;

    float acc[2][8][4];
    gemm128x128(X, W, m0, n0, smh, acc);

    const int lane = threadIdx.x & 31;
    const int w    = threadIdx.x >> 5;
    const int wm   = w >> 1, wn = w & 1;
    const int gr   = lane >> 2, gq = lane & 3;

#pragma unroll
    for (int nt = 0; nt < 8; nt++) {
        int col = n0 + wn * 64 + nt * 8 + gq * 2;
        float b0 = __ldg(bias + col);
        float b1 = __ldg(bias + col + 1);
        int h = col >> 6, d = col & 63;
#pragma unroll
        for (int mt = 0; mt < 2; mt++) {
#pragma unroll
            for (int half = 0; half < 2; half++) {
                int row = m0 + wm * 32 + mt * 16 + gr + half * 8;
                int bi = row >> 11, t = row & (TT - 1);
                uint32_t val = h2pack((acc[mt][nt][half * 2 + 0] + b0) * scale,
                                      (acc[mt][nt][half * 2 + 1] + b1) * scale);
                *(uint32_t*)(Out + ((((size_t)(bi * HH + h)) * TT + t) << 6) + d) = val;
            }
        }
    }
}

// ---------------------------------------------------------------------------
// Output projection: out = g_O @ Wo + bo (final, fp32 out)
// ---------------------------------------------------------------------------
__global__ __launch_bounds__(256, 2)
void out_kernel(const float* __restrict__ bo, float* __restrict__ out)
{
    extern __shared__ __half smh[];
    const int m0 = blockIdx.x * 128;
    const int n0 = blockIdx.y * 128;

    float acc[2][8][4];
    gemm128x128(g_O, g_Wh + (size_t)3 * DD * DD, m0, n0, smh, acc);

    const int lane = threadIdx.x & 31;
    const int w    = threadIdx.x >> 5;
    const int wm   = w >> 1, wn = w & 1;
    const int gr   = lane >> 2, gq = lane & 3;

#pragma unroll
    for (int nt = 0; nt < 8; nt++) {
        int col = n0 + wn * 64 + nt * 8 + gq * 2;
        float b0 = __ldg(bo + col);
        float b1 = __ldg(bo + col + 1);
#pragma unroll
        for (int mt = 0; mt < 2; mt++) {
#pragma unroll
            for (int half = 0; half < 2; half++) {
                int row = m0 + wm * 32 + mt * 16 + gr + half * 8;
                float2 val;
                val.x = acc[mt][nt][half * 2 + 0] + b0;
                val.y = acc[mt][nt][half * 2 + 1] + b1;
                *(float2*)(out + (size_t)row * DD + col) = val;
            }
        }
    }
}

// ---------------------------------------------------------------------------
// fp16 flash attention, log2-domain softmax (packed f16x2 ex2), ALiBi band
// skipping, diagonal-outward tile order, vote-skipped rescale.
// grid (T/64=32, 16, 2), block 128 (4 warps, 16 q-rows each).
// ---------------------------------------------------------------------------
#define LDK 72
#define LDV 72
#define KVH (64*LDK + 64*LDV)          // 9216 halves per buffer
#define ALIBI_MARGIN 27.0f
#define ATTN_SMEM_BYTES (3*KVH*2)      // 55296
#define ONESH2 0x3C003C00u             // half2(1.0, 1.0)

// Diagonal-outward order over [lo, hi] containing qt, each tile exactly once.
__device__ __forceinline__ int tile_at(int it, int qt, int lo, int hi) {
    const int left  = qt - lo;
    const int right = hi - qt;
    const int m = (left < right) ? left : right;
    if (it <= 2 * m) {
        const int d = (it + 1) >> 1;
        return (it & 1) ? (qt - d) : (qt + d);
    }
    const int rem = it - 2 * m;
    return (left > right) ? (qt - m - rem) : (qt + m + rem);
}

__global__ __launch_bounds__(128, 4)
void attn_kernel()
{
    extern __shared__ __half smh[];

    const int qt = blockIdx.x;
    const int h  = HH - 1 - blockIdx.y;   // heavy heads first
    const int b  = blockIdx.z;

    const int tid  = threadIdx.x;
    const int lane = tid & 31;
    const int w    = tid >> 5;            // 0..3
    const int gr   = lane >> 2;
    const int gq   = lane & 3;

    const float slope    = exp2f(-0.5f * (float)(h + 1));
    const float slope_l2 = slope * LOG2E;
    const int q0 = qt * 64;

    const int band  = (int)(ALIBI_MARGIN / slope);
    const int kt_lo = max(0, (q0 - band) >> 6);
    const int kt_hi = min(TT / 64 - 1, (q0 + 63 + band) >> 6);
    const int n_tiles = kt_hi - kt_lo + 1;

    const __half* Qb = g_Q + (((size_t)(b * HH + h)) * TT + q0 + w * 16) * HD;
    const __half* Kb = g_K + (((size_t)(b * HH + h)) * TT) * HD;
    const __half* Vb = g_V + (((size_t)(b * HH + h)) * TT) * HD;

    const uint32_t sbase = smem_u32(smh);

    auto ISSUE_K = [&](int kt, int buf) {
        const uint32_t Kd = sbase + (uint32_t)(buf * KVH) * 2;
        const __half* Kg = Kb + (size_t)kt * 64 * HD;
#pragma unroll
        for (int j = 0; j < 4; j++) {
            const int f = tid + j * 128;
            const int r = f >> 3, c = f & 7;
            cp16(Kd + (uint32_t)(r * LDK + c * 8) * 2, Kg + r * HD + c * 8);
        }
    };
    auto ISSUE_V = [&](int kt, int buf) {
        const uint32_t Vd = sbase + (uint32_t)(buf * KVH + 64 * LDK) * 2;
        const __half* Vg = Vb + (size_t)kt * 64 * HD;
#pragma unroll
        for (int j = 0; j < 4; j++) {
            const int f = tid + j * 128;
            const int r = f >> 3, c = f & 7;
            cp16(Vd + (uint32_t)(r * LDV + c * 8) * 2, Vg + r * HD + c * 8);
        }
    };

    // Q fragments (fp16, pre-scaled by 0.125*log2e), loaded once from gmem
    uint32_t qf[4][4];
#pragma unroll
    for (int kk = 0; kk < 4; kk++) {
        qf[kk][0] = *(const uint32_t*)(Qb + (gr)     * HD + kk * 16 + gq * 2);
        qf[kk][1] = *(const uint32_t*)(Qb + (gr + 8) * HD + kk * 16 + gq * 2);
        qf[kk][2] = *(const uint32_t*)(Qb + (gr)     * HD + kk * 16 + gq * 2 + 8);
        qf[kk][3] = *(const uint32_t*)(Qb + (gr + 8) * HD + kk * 16 + gq * 2 + 8);
    }

    // oacc[0..7] = O tiles; oacc[8] = l accumulator (P @ ones column)
    float oacc[9][4];
#pragma unroll
    for (int nt = 0; nt < 9; nt++)
#pragma unroll
        for (int i = 0; i < 4; i++) oacc[nt][i] = 0.0f;

    float m_lo = -INFINITY, m_hi = -INFINITY;

    const int qrow_lo = q0 + w * 16 + gr;
    const int qrow_hi = qrow_lo + 8;
    const float qlo_f = (float)qrow_lo;
    const float qhi_f = (float)qrow_hi;

    const int l15 = lane & 15;
    const int l7  = lane & 7;
    const int hi16 = (lane >> 4) << 3;
    const int mid8 = ((lane >> 3) & 1) << 3;

    {
        const int t0 = tile_at(0, qt, kt_lo, kt_hi);
        ISSUE_K(t0, 0); ISSUE_V(t0, 0); CP_COMMIT();
        if (n_tiles > 1) {
            const int t1 = tile_at(1, qt, kt_lo, kt_hi);
            ISSUE_K(t1, 1); ISSUE_V(t1, 1);
        }
        CP_COMMIT();
    }

#pragma unroll 1
    for (int it = 0; it < n_tiles; it++) {
        const int kt = tile_at(it, qt, kt_lo, kt_hi);
        CP_WAIT(1);
        __syncthreads();

        const uint32_t Ksmb = sbase + (uint32_t)((it % 3) * KVH) * 2;
        const uint32_t Vsmb = Ksmb + (uint32_t)(64 * LDK) * 2;
        const int nextbuf = (it + 2) % 3;
        const bool havenext = (it + 2 < n_tiles);
        const int nextkt = havenext ? tile_at(it + 2, qt, kt_lo, kt_hi) : 0;

        // ---- S = Q @ K^T (log2 domain) ----
        float sacc[8][4];
#pragma unroll
        for (int nt = 0; nt < 8; nt++)
            sacc[nt][0] = sacc[nt][1] = sacc[nt][2] = sacc[nt][3] = 0.0f;

#pragma unroll
        for (int kk = 0; kk < 4; kk++) {
            uint32_t kb[4][4];
#pragma unroll
            for (int p = 0; p < 4; p++) {
                const int row = p * 16 + hi16 + l7;
                const int col = kk * 16 + mid8;
                ldm_x4(kb[p], Ksmb + (uint32_t)(row * LDK + col) * 2);
            }
#pragma unroll
            for (int nt = 0; nt < 8; nt++) {
                const int p = nt >> 1, o = (nt & 1) * 2;
                mma_f16(sacc[nt], qf[kk], kb[p][o], kb[p][o + 1]);
            }
            if (kk == 0) {
                if (havenext) ISSUE_K(nextkt, nextbuf);
            } else if (kk == 1) {
                if (havenext) ISSUE_V(nextkt, nextbuf);
                CP_COMMIT();
            }
        }

        // ---- ALiBi bias + row max ----
        const bool diag = (kt == qt);
        const float c  = diag ? 0.0f : ((kt < qt) ? slope_l2 : -slope_l2);
        const float rowc_lo = -c * qlo_f;
        const float rowc_hi = -c * qhi_f;

        float mx_lo = -INFINITY, mx_hi = -INFINITY;
        if (diag) {
            const int jb = kt * 64 + gq * 2;
#pragma unroll
            for (int nt = 0; nt < 8; nt++) {
                float j0 = (float)(jb + nt * 8);
                float j1 = j0 + 1.0f;
                sacc[nt][0] -= slope_l2 * fabsf(qlo_f - j0);
                sacc[nt][1] -= slope_l2 * fabsf(qlo_f - j1);
                sacc[nt][2] -= slope_l2 * fabsf(qhi_f - j0);
                sacc[nt][3] -= slope_l2 * fabsf(qhi_f - j1);
                mx_lo = fmaxf(mx_lo, fmaxf(sacc[nt][0], sacc[nt][1]));
                mx_hi = fmaxf(mx_hi, fmaxf(sacc[nt][2], sacc[nt][3]));
            }
        } else {
            float cj = c * (float)(kt * 64 + gq * 2);
            const float c8 = c * 8.0f;
#pragma unroll
            for (int nt = 0; nt < 8; nt++) {
                const float cj1 = cj + c;
                sacc[nt][0] += cj;
                sacc[nt][1] += cj1;
                sacc[nt][2] += cj;
                sacc[nt][3] += cj1;
                mx_lo = fmaxf(mx_lo, fmaxf(sacc[nt][0], sacc[nt][1]));
                mx_hi = fmaxf(mx_hi, fmaxf(sacc[nt][2], sacc[nt][3]));
                cj += c8;
            }
            mx_lo += rowc_lo;
            mx_hi += rowc_hi;
        }
        mx_lo = fmaxf(mx_lo, __shfl_xor_sync(0xffffffffu, mx_lo, 1));
        mx_lo = fmaxf(mx_lo, __shfl_xor_sync(0xffffffffu, mx_lo, 2));
        mx_hi = fmaxf(mx_hi, __shfl_xor_sync(0xffffffffu, mx_hi, 1));
        mx_hi = fmaxf(mx_hi, __shfl_xor_sync(0xffffffffu, mx_hi, 2));

        float mn_lo = fmaxf(m_lo, mx_lo);
        float mn_hi = fmaxf(m_hi, mx_hi);
        float corr_lo = ex2(m_lo - mn_lo);
        float corr_hi = ex2(m_hi - mn_hi);
        m_lo = mn_lo; m_hi = mn_hi;

        const float Klo = mn_lo - rowc_lo;
        const float Khi = mn_hi - rowc_hi;

        // ---- exp via packed f16x2 MUFU: deltas -> half2 -> ex2 -> P frags ----
        uint32_t pl[8], ph[8];
#pragma unroll
        for (int nt = 0; nt < 8; nt++) {
            pl[nt] = ex2_h2(h2pack(sacc[nt][0] - Klo, sacc[nt][1] - Klo));
            ph[nt] = ex2_h2(h2pack(sacc[nt][2] - Khi, sacc[nt][3] - Khi));
        }

        // rescale O/l only when some row's max moved (exact skip otherwise)
        const bool need = (corr_lo != 1.0f) || (corr_hi != 1.0f);
        if (__any_sync(0xffffffffu, need)) {
#pragma unroll
            for (int nt = 0; nt < 9; nt++) {
                oacc[nt][0] *= corr_lo;
                oacc[nt][1] *= corr_lo;
                oacc[nt][2] *= corr_hi;
                oacc[nt][3] *= corr_hi;
            }
        }

        // ---- O += P @ V ; l += P @ 1 ----
#pragma unroll
        for (int kk = 0; kk < 4; kk++) {
            uint32_t pa[4];
            pa[0] = pl[2 * kk];
            pa[1] = ph[2 * kk];
            pa[2] = pl[2 * kk + 1];
            pa[3] = ph[2 * kk + 1];
            uint32_t vb[4][4];
#pragma unroll
            for (int np = 0; np < 4; np++) {
                const int row = kk * 16 + l15;
                const int col = np * 16 + hi16;
                ldm_x4t(vb[np], Vsmb + (uint32_t)(row * LDV + col) * 2);
            }
#pragma unroll
            for (int nt = 0; nt < 8; nt++) {
                const int np = nt >> 1, o = (nt & 1) * 2;
                mma_f16(oacc[nt], pa, vb[np][o], vb[np][o + 1]);
            }
            mma_f16(oacc[8], pa, ONESH2, ONESH2);   // row sums of P
        }
    }

    // epilogue: O /= l
    float inv_lo = 1.0f / oacc[8][0];
    float inv_hi = 1.0f / oacc[8][2];
    __half* Ob = g_O + ((size_t)(b * TT + q0 + w * 16)) * DD + h * HD;
#pragma unroll
    for (int nt = 0; nt < 8; nt++) {
        *(uint32_t*)(Ob + (size_t)(gr)     * DD + nt * 8 + gq * 2) =
            h2pack(oacc[nt][0] * inv_lo, oacc[nt][1] * inv_lo);
        *(uint32_t*)(Ob + (size_t)(gr + 8) * DD + nt * 8 + gq * 2) =
            h2pack(oacc[nt][2] * inv_hi, oacc[nt][3] * inv_hi);
    }
}

// ---------------------------------------------------------------------------
extern "C" void kernel_launch(void* const* d_in, const int* in_sizes, int n_in,
                              void* d_out, int out_size)
{
    const float* query = (const float*)d_in[0];
    const float* key_  = (const float*)d_in[1];
    const float* value = (const float*)d_in[2];
    const float* Wq    = (const float*)d_in[3];
    const float* bq    = (const float*)d_in[4];
    const float* Wk    = (const float*)d_in[5];
    const float* bk    = (const float*)d_in[6];
    const float* Wv    = (const float*)d_in[7];
    const float* bv    = (const float*)d_in[8];
    const float* Wo    = (const float*)d_in[9];
    const float* bo    = (const float*)d_in[10];
    float* out = (float*)d_out;

    static int attr_done = 0;
    if (!attr_done) {
        cudaFuncSetAttribute(qkv_kernel, cudaFuncAttributeMaxDynamicSharedMemorySize,
                             GEMM_SMEM_BYTES);
        cudaFuncSetAttribute(out_kernel, cudaFuncAttributeMaxDynamicSharedMemorySize,
                             GEMM_SMEM_BYTES);
        cudaFuncSetAttribute(attn_kernel, cudaFuncAttributeMaxDynamicSharedMemorySize,
                             ATTN_SMEM_BYTES);
        attr_done = 1;
    }

    round_all<<<(XPAIRS + WPAIRS) / 256, 256>>>(
        (const float4*)query, (const float4*)key_, (const float4*)value,
        (const float4*)Wq, (const float4*)Wk, (const float4*)Wv, (const float4*)Wo);

    dim3 gqkv(MROWS / 128, DD / 128, 3);
    qkv_kernel<<<gqkv, 256, GEMM_SMEM_BYTES>>>(bq, bk, bv);

    dim3 gattn(TT / 64, HH, BB);
    attn_kernel<<<gattn, 128, ATTN_SMEM_BYTES>>>();

    dim3 gout(MROWS / 128, DD / 128);
    out_kernel<<<gout, 256, GEMM_SMEM_BYTES>>>(bo, out);
}

// round 17
// speedup vs baseline: 1.0539x; 1.0219x over previous
#include <cuda_runtime.h>
#include <cuda_fp16.h>
#include <math.h>
#include <stdint.h>

// Problem constants
#define BB 2
#define TT 2048
#define DD 1024
#define HH 16
#define HD 64
#define MROWS (BB*TT)        // 4096
#define LOG2E 1.44269504088896340736f

// Scratch (device globals; allocation is forbidden). All fp16.
__device__ __half g_Q[BB*HH*TT*HD];   // [B,H,T,hd], scaled by 0.125*log2e
__device__ __half g_K[BB*HH*TT*HD];
__device__ __half g_V[BB*HH*TT*HD];
__device__ __half g_O[MROWS*DD];      // [B*T, D]
__device__ __half g_Xh[3*MROWS*DD];   // fp16 query/key/value
__device__ __half g_Wh[4*DD*DD];      // fp16 Wq/Wk/Wv/Wo

// ---------------------------------------------------------------------------
// helpers
// ---------------------------------------------------------------------------
__device__ __forceinline__ uint32_t smem_u32(const void* p) {
    uint32_t a;
    asm("{ .reg .u64 t; cvta.to.shared.u64 t, %1; cvt.u32.u64 %0, t; }"
        : "=r"(a) : "l"(p));
    return a;
}
// pack two floats into half2 (lo = first arg)
__device__ __forceinline__ uint32_t h2pack(float lo, float hi) {
    uint32_t r;
    asm("cvt.rn.f16x2.f32 %0, %1, %2;" : "=r"(r) : "f"(hi), "f"(lo));
    return r;
}
__device__ __forceinline__ float ex2(float x) {
    float y;
    asm("ex2.approx.f32 %0, %1;" : "=f"(y) : "f"(x));
    return y;
}
// packed half2 exp2
__device__ __forceinline__ uint32_t ex2_h2(uint32_t x) {
    uint32_t y;
    asm("ex2.approx.f16x2 %0, %1;" : "=r"(y) : "r"(x));
    return y;
}
__device__ __forceinline__ void cp16(uint32_t dst, const void* src) {
    asm volatile("cp.async.cg.shared.global [%0], [%1], 16;"
                 :: "r"(dst), "l"(src));
}
#define CP_COMMIT() asm volatile("cp.async.commit_group;" ::: "memory")
#define CP_WAIT(N)  asm volatile("cp.async.wait_group %0;" :: "n"(N) : "memory")

__device__ __forceinline__ void ldm_x4(uint32_t r[4], uint32_t addr) {
    asm volatile("ldmatrix.sync.aligned.m8n8.x4.shared.b16 {%0,%1,%2,%3}, [%4];"
                 : "=r"(r[0]), "=r"(r[1]), "=r"(r[2]), "=r"(r[3]) : "r"(addr));
}
__device__ __forceinline__ void ldm_x4t(uint32_t r[4], uint32_t addr) {
    asm volatile("ldmatrix.sync.aligned.m8n8.x4.trans.shared.b16 {%0,%1,%2,%3}, [%4];"
                 : "=r"(r[0]), "=r"(r[1]), "=r"(r[2]), "=r"(r[3]) : "r"(addr));
}
// D += A(16x16) * B(16x8), fp16 in, f32 accum
__device__ __forceinline__ void mma_f16(float c[4], const uint32_t a[4],
                                        uint32_t b0, uint32_t b1) {
    asm volatile(
        "mma.sync.aligned.m16n8k16.row.col.f32.f16.f16.f32 "
        "{%0,%1,%2,%3},{%4,%5,%6,%7},{%8,%9},{%0,%1,%2,%3};\n"
        : "+f"(c[0]), "+f"(c[1]), "+f"(c[2]), "+f"(c[3])
        : "r"(a[0]), "r"(a[1]), "r"(a[2]), "r"(a[3]), "r"(b0), "r"(b1));
}

// ---------------------------------------------------------------------------
// Pre-pass: convert inputs and weights to fp16 (single kernel).
// ---------------------------------------------------------------------------
#define XPER (MROWS*DD/8)      // 524288 pairs per X tensor
#define WPER (DD*DD/8)         // 131072 pairs per W tensor
#define XPAIRS (3*XPER)
#define WPAIRS (4*WPER)

__global__ __launch_bounds__(256)
void round_all(const float4* __restrict__ q, const float4* __restrict__ k,
               const float4* __restrict__ v,
               const float4* __restrict__ w0, const float4* __restrict__ w1,
               const float4* __restrict__ w2, const float4* __restrict__ w3)
{
    int e = blockIdx.x * 256 + threadIdx.x;
    const float4* src;
    uint4* dst;
    int off;
    if (e < XPAIRS) {
        int z = e / XPER;
        off = e - z * XPER;
        src = (z == 0) ? q : (z == 1) ? k : v;
        dst = (uint4*)(g_Xh + (size_t)z * MROWS * DD);
    } else {
        int e2 = e - XPAIRS;
        int z = e2 / WPER;
        off = e2 - z * WPER;
        src = (z == 0) ? w0 : (z == 1) ? w1 : (z == 2) ? w2 : w3;
        dst = (uint4*)(g_Wh + (size_t)z * DD * DD);
    }
    float4 a = src[2 * off], b = src[2 * off + 1];
    uint4 o;
    o.x = h2pack(a.x, a.y); o.y = h2pack(a.z, a.w);
    o.z = h2pack(b.x, b.y); o.w = h2pack(b.z, b.w);
    dst[off] = o;
}

// ---------------------------------------------------------------------------
// fp16 GEMM core: 128x128 tile, BK=64, 3-stage cp.async, ldmatrix frags.
// cp.async issue split: A-half after kk=0's mmas, B-half+commit after kk=1's.
// ---------------------------------------------------------------------------
#define LDA 72
#define LDW 136
#define ASTG (128*LDA)             // 9216 halves
#define BSTG (64*LDW)              // 8704 halves
#define STG  (ASTG+BSTG)           // 17920 halves
#define GEMM_SMEM_BYTES (3*STG*2)  // 107520

__device__ __forceinline__ void gemm128x128(
    const __half* __restrict__ X, const __half* __restrict__ W,
    int m0, int n0, __half* sm, float acc[2][8][4])
{
    const int tid  = threadIdx.x;
    const int lane = tid & 31;
    const int w    = tid >> 5;
    const int wm   = w >> 1;
    const int wn   = w & 1;

    const uint32_t sbase = smem_u32(sm);

#pragma unroll
    for (int mt = 0; mt < 2; mt++)
#pragma unroll
        for (int nt = 0; nt < 8; nt++)
#pragma unroll
            for (int i = 0; i < 4; i++) acc[mt][nt][i] = 0.0f;

    auto ISSUE_A = [&](int s) {
        const int k0 = s * 64;
        const uint32_t Ab = sbase + (uint32_t)((s % 3) * STG) * 2;
#pragma unroll
        for (int j = 0; j < 4; j++) {
            const int f = tid + j * 256;
            const int ra = f >> 3, ca = f & 7;
            cp16(Ab + (uint32_t)(ra * LDA + ca * 8) * 2,
                 X + (size_t)(m0 + ra) * DD + k0 + ca * 8);
        }
    };
    auto ISSUE_B = [&](int s) {
        const int k0 = s * 64;
        const uint32_t Bb = sbase + (uint32_t)((s % 3) * STG) * 2 + ASTG * 2;
#pragma unroll
        for (int j = 0; j < 4; j++) {
            const int f = tid + j * 256;
            const int rb = f >> 4, cb = f & 15;
            cp16(Bb + (uint32_t)(rb * LDW + cb * 8) * 2,
                 W + (size_t)(k0 + rb) * DD + n0 + cb * 8);
        }
    };

    ISSUE_A(0); ISSUE_B(0); CP_COMMIT();
    ISSUE_A(1); ISSUE_B(1); CP_COMMIT();

    const int lrow = lane & 15;
    const int lcol = (lane >> 4) << 3;

#pragma unroll 1
    for (int s = 0; s < 16; s++) {
        CP_WAIT(1);
        __syncthreads();

        const uint32_t Ab = sbase + (uint32_t)((s % 3) * STG) * 2;
        const uint32_t Bb = Ab + ASTG * 2;

#pragma unroll
        for (int kk = 0; kk < 4; kk++) {
            uint32_t a[2][4];
#pragma unroll
            for (int mt = 0; mt < 2; mt++) {
                const int r = wm * 32 + mt * 16;
                ldm_x4(a[mt], Ab + (uint32_t)((r + lrow) * LDA + kk * 16 + lcol) * 2);
            }
            uint32_t bb[4][4];
#pragma unroll
            for (int np = 0; np < 4; np++) {
                const int col = wn * 64 + np * 16 + lcol;
                ldm_x4t(bb[np], Bb + (uint32_t)((kk * 16 + lrow) * LDW + col) * 2);
            }
#pragma unroll
            for (int nt = 0; nt < 8; nt++) {
                const int np = nt >> 1, o = (nt & 1) * 2;
                mma_f16(acc[0][nt], a[0], bb[np][o], bb[np][o + 1]);
                mma_f16(acc[1][nt], a[1], bb[np][o], bb[np][o + 1]);
            }
            if (kk == 0) {
                if (s + 2 < 16) ISSUE_A(s + 2);
            } else if (kk == 1) {
                if (s + 2 < 16) ISSUE_B(s + 2);
                CP_COMMIT();
            }
        }
    }
}

// ---------------------------------------------------------------------------
// QKV projection: grid (32, 8, 3), block 256. Outputs fp16 (Q pre-scaled).
// ---------------------------------------------------------------------------
__global__ __launch_bounds__(256, 2)
void qkv_kernel(const float* __restrict__ bq, const float* __restrict__ bk,
                const float* __restrict__ bv)
{
    extern __shared__ __half smh[];
    const int z = blockIdx.z;
    const __half* X   = g_Xh + (size_t)z * MROWS * DD;
    const __half* W   = g_Wh + (size_t)z * DD * DD;
    const float* bias = (z == 0) ? bq : (z == 1) ? bk : bv;
    __half* Out       = (z == 0) ? g_Q : (z == 1) ? g_K : g_V;
    const float scale = (z == 0) ? 0.125f * LOG2E : 1.0f;

    const int m0 = blockIdx.x * 128;
    const int n0 = blockIdx.y * 128;

    float acc[2][8][4];
    gemm128x128(X, W, m0, n0, smh, acc);

    const int lane = threadIdx.x & 31;
    const int w    = threadIdx.x >> 5;
    const int wm   = w >> 1, wn = w & 1;
    const int gr   = lane >> 2, gq = lane & 3;

#pragma unroll
    for (int nt = 0; nt < 8; nt++) {
        int col = n0 + wn * 64 + nt * 8 + gq * 2;
        float b0 = __ldg(bias + col);
        float b1 = __ldg(bias + col + 1);
        int h = col >> 6, d = col & 63;
#pragma unroll
        for (int mt = 0; mt < 2; mt++) {
#pragma unroll
            for (int half = 0; half < 2; half++) {
                int row = m0 + wm * 32 + mt * 16 + gr + half * 8;
                int bi = row >> 11, t = row & (TT - 1);
                uint32_t val = h2pack((acc[mt][nt][half * 2 + 0] + b0) * scale,
                                      (acc[mt][nt][half * 2 + 1] + b1) * scale);
                *(uint32_t*)(Out + ((((size_t)(bi * HH + h)) * TT + t) << 6) + d) = val;
            }
        }
    }
}

// ---------------------------------------------------------------------------
// Output projection: out = g_O @ Wo + bo (final, fp32 out)
// ---------------------------------------------------------------------------
__global__ __launch_bounds__(256, 2)
void out_kernel(const float* __restrict__ bo, float* __restrict__ out)
{
    extern __shared__ __half smh[];
    const int m0 = blockIdx.x * 128;
    const int n0 = blockIdx.y * 128;

    float acc[2][8][4];
    gemm128x128(g_O, g_Wh + (size_t)3 * DD * DD, m0, n0, smh, acc);

    const int lane = threadIdx.x & 31;
    const int w    = threadIdx.x >> 5;
    const int wm   = w >> 1, wn = w & 1;
    const int gr   = lane >> 2, gq = lane & 3;

#pragma unroll
    for (int nt = 0; nt < 8; nt++) {
        int col = n0 + wn * 64 + nt * 8 + gq * 2;
        float b0 = __ldg(bo + col);
        float b1 = __ldg(bo + col + 1);
#pragma unroll
        for (int mt = 0; mt < 2; mt++) {
#pragma unroll
            for (int half = 0; half < 2; half++) {
                int row = m0 + wm * 32 + mt * 16 + gr + half * 8;
                float2 val;
                val.x = acc[mt][nt][half * 2 + 0] + b0;
                val.y = acc[mt][nt][half * 2 + 1] + b1;
                *(float2*)(out + (size_t)row * DD + col) = val;
            }
        }
    }
}

// ---------------------------------------------------------------------------
// fp16 flash attention, log2-domain softmax (packed f16x2 ex2), ALiBi band
// skipping, diagonal-outward tile order, vote-skipped rescale, and DYNAMIC
// tile skip: if a tile's entire row max is >=22 (log2) below the running
// max, its probabilities are < 2^-22 each (<= ~1.5e-5 of l per tile) and the
// exp + PV work is skipped. grid (T/64=32, 16, 2), block 128 (4 warps).
// ---------------------------------------------------------------------------
#define LDK 72
#define LDV 72
#define KVH (64*LDK + 64*LDV)          // 9216 halves per buffer
#define ALIBI_MARGIN 27.0f
#define SKIP_THRESH 22.0f
#define ATTN_SMEM_BYTES (3*KVH*2)      // 55296
#define ONESH2 0x3C003C00u             // half2(1.0, 1.0)

// Diagonal-outward order over [lo, hi] containing qt, each tile exactly once.
__device__ __forceinline__ int tile_at(int it, int qt, int lo, int hi) {
    const int left  = qt - lo;
    const int right = hi - qt;
    const int m = (left < right) ? left : right;
    if (it <= 2 * m) {
        const int d = (it + 1) >> 1;
        return (it & 1) ? (qt - d) : (qt + d);
    }
    const int rem = it - 2 * m;
    return (left > right) ? (qt - m - rem) : (qt + m + rem);
}

__global__ __launch_bounds__(128, 4)
void attn_kernel()
{
    extern __shared__ __half smh[];

    const int qt = blockIdx.x;
    const int h  = HH - 1 - blockIdx.y;   // heavy heads first
    const int b  = blockIdx.z;

    const int tid  = threadIdx.x;
    const int lane = tid & 31;
    const int w    = tid >> 5;            // 0..3
    const int gr   = lane >> 2;
    const int gq   = lane & 3;

    const float slope    = exp2f(-0.5f * (float)(h + 1));
    const float slope_l2 = slope * LOG2E;
    const int q0 = qt * 64;

    const int band  = (int)(ALIBI_MARGIN / slope);
    const int kt_lo = max(0, (q0 - band) >> 6);
    const int kt_hi = min(TT / 64 - 1, (q0 + 63 + band) >> 6);
    const int n_tiles = kt_hi - kt_lo + 1;

    const __half* Qb = g_Q + (((size_t)(b * HH + h)) * TT + q0 + w * 16) * HD;
    const __half* Kb = g_K + (((size_t)(b * HH + h)) * TT) * HD;
    const __half* Vb = g_V + (((size_t)(b * HH + h)) * TT) * HD;

    const uint32_t sbase = smem_u32(smh);

    auto ISSUE_K = [&](int kt, int buf) {
        const uint32_t Kd = sbase + (uint32_t)(buf * KVH) * 2;
        const __half* Kg = Kb + (size_t)kt * 64 * HD;
#pragma unroll
        for (int j = 0; j < 4; j++) {
            const int f = tid + j * 128;
            const int r = f >> 3, c = f & 7;
            cp16(Kd + (uint32_t)(r * LDK + c * 8) * 2, Kg + r * HD + c * 8);
        }
    };
    auto ISSUE_V = [&](int kt, int buf) {
        const uint32_t Vd = sbase + (uint32_t)(buf * KVH + 64 * LDK) * 2;
        const __half* Vg = Vb + (size_t)kt * 64 * HD;
#pragma unroll
        for (int j = 0; j < 4; j++) {
            const int f = tid + j * 128;
            const int r = f >> 3, c = f & 7;
            cp16(Vd + (uint32_t)(r * LDV + c * 8) * 2, Vg + r * HD + c * 8);
        }
    };

    // Q fragments (fp16, pre-scaled by 0.125*log2e), loaded once from gmem
    uint32_t qf[4][4];
#pragma unroll
    for (int kk = 0; kk < 4; kk++) {
        qf[kk][0] = *(const uint32_t*)(Qb + (gr)     * HD + kk * 16 + gq * 2);
        qf[kk][1] = *(const uint32_t*)(Qb + (gr + 8) * HD + kk * 16 + gq * 2);
        qf[kk][2] = *(const uint32_t*)(Qb + (gr)     * HD + kk * 16 + gq * 2 + 8);
        qf[kk][3] = *(const uint32_t*)(Qb + (gr + 8) * HD + kk * 16 + gq * 2 + 8);
    }

    // oacc[0..7] = O tiles; oacc[8] = l accumulator (P @ ones column)
    float oacc[9][4];
#pragma unroll
    for (int nt = 0; nt < 9; nt++)
#pragma unroll
        for (int i = 0; i < 4; i++) oacc[nt][i] = 0.0f;

    float m_lo = -INFINITY, m_hi = -INFINITY;

    const int qrow_lo = q0 + w * 16 + gr;
    const int qrow_hi = qrow_lo + 8;
    const float qlo_f = (float)qrow_lo;
    const float qhi_f = (float)qrow_hi;

    const int l15 = lane & 15;
    const int l7  = lane & 7;
    const int hi16 = (lane >> 4) << 3;
    const int mid8 = ((lane >> 3) & 1) << 3;

    {
        const int t0 = tile_at(0, qt, kt_lo, kt_hi);
        ISSUE_K(t0, 0); ISSUE_V(t0, 0); CP_COMMIT();
        if (n_tiles > 1) {
            const int t1 = tile_at(1, qt, kt_lo, kt_hi);
            ISSUE_K(t1, 1); ISSUE_V(t1, 1);
        }
        CP_COMMIT();
    }

#pragma unroll 1
    for (int it = 0; it < n_tiles; it++) {
        const int kt = tile_at(it, qt, kt_lo, kt_hi);
        CP_WAIT(1);
        __syncthreads();

        const uint32_t Ksmb = sbase + (uint32_t)((it % 3) * KVH) * 2;
        const uint32_t Vsmb = Ksmb + (uint32_t)(64 * LDK) * 2;
        const int nextbuf = (it + 2) % 3;
        const bool havenext = (it + 2 < n_tiles);
        const int nextkt = havenext ? tile_at(it + 2, qt, kt_lo, kt_hi) : 0;

        // ---- S = Q @ K^T (log2 domain) ----
        float sacc[8][4];
#pragma unroll
        for (int nt = 0; nt < 8; nt++)
            sacc[nt][0] = sacc[nt][1] = sacc[nt][2] = sacc[nt][3] = 0.0f;

#pragma unroll
        for (int kk = 0; kk < 4; kk++) {
            uint32_t kb[4][4];
#pragma unroll
            for (int p = 0; p < 4; p++) {
                const int row = p * 16 + hi16 + l7;
                const int col = kk * 16 + mid8;
                ldm_x4(kb[p], Ksmb + (uint32_t)(row * LDK + col) * 2);
            }
#pragma unroll
            for (int nt = 0; nt < 8; nt++) {
                const int p = nt >> 1, o = (nt & 1) * 2;
                mma_f16(sacc[nt], qf[kk], kb[p][o], kb[p][o + 1]);
            }
            if (kk == 0) {
                if (havenext) ISSUE_K(nextkt, nextbuf);
            } else if (kk == 1) {
                if (havenext) ISSUE_V(nextkt, nextbuf);
                CP_COMMIT();
            }
        }

        // ---- ALiBi bias + row max ----
        const bool diag = (kt == qt);
        const float c  = diag ? 0.0f : ((kt < qt) ? slope_l2 : -slope_l2);
        const float rowc_lo = -c * qlo_f;
        const float rowc_hi = -c * qhi_f;

        float mx_lo = -INFINITY, mx_hi = -INFINITY;
        if (diag) {
            const int jb = kt * 64 + gq * 2;
#pragma unroll
            for (int nt = 0; nt < 8; nt++) {
                float j0 = (float)(jb + nt * 8);
                float j1 = j0 + 1.0f;
                sacc[nt][0] -= slope_l2 * fabsf(qlo_f - j0);
                sacc[nt][1] -= slope_l2 * fabsf(qlo_f - j1);
                sacc[nt][2] -= slope_l2 * fabsf(qhi_f - j0);
                sacc[nt][3] -= slope_l2 * fabsf(qhi_f - j1);
                mx_lo = fmaxf(mx_lo, fmaxf(sacc[nt][0], sacc[nt][1]));
                mx_hi = fmaxf(mx_hi, fmaxf(sacc[nt][2], sacc[nt][3]));
            }
        } else {
            float cj = c * (float)(kt * 64 + gq * 2);
            const float c8 = c * 8.0f;
#pragma unroll
            for (int nt = 0; nt < 8; nt++) {
                const float cj1 = cj + c;
                sacc[nt][0] += cj;
                sacc[nt][1] += cj1;
                sacc[nt][2] += cj;
                sacc[nt][3] += cj1;
                mx_lo = fmaxf(mx_lo, fmaxf(sacc[nt][0], sacc[nt][1]));
                mx_hi = fmaxf(mx_hi, fmaxf(sacc[nt][2], sacc[nt][3]));
                cj += c8;
            }
            mx_lo += rowc_lo;
            mx_hi += rowc_hi;
        }
        mx_lo = fmaxf(mx_lo, __shfl_xor_sync(0xffffffffu, mx_lo, 1));
        mx_lo = fmaxf(mx_lo, __shfl_xor_sync(0xffffffffu, mx_lo, 2));
        mx_hi = fmaxf(mx_hi, __shfl_xor_sync(0xffffffffu, mx_hi, 1));
        mx_hi = fmaxf(mx_hi, __shfl_xor_sync(0xffffffffu, mx_hi, 2));

        // ---- dynamic tile skip: all probabilities < 2^-SKIP_THRESH ----
        if (__all_sync(0xffffffffu,
                       (mx_lo < m_lo - SKIP_THRESH) &&
                       (mx_hi < m_hi - SKIP_THRESH)))
            continue;   // prefetch already issued & committed above

        float mn_lo = fmaxf(m_lo, mx_lo);
        float mn_hi = fmaxf(m_hi, mx_hi);
        float corr_lo = ex2(m_lo - mn_lo);
        float corr_hi = ex2(m_hi - mn_hi);
        m_lo = mn_lo; m_hi = mn_hi;

        const float Klo = mn_lo - rowc_lo;
        const float Khi = mn_hi - rowc_hi;

        // ---- exp via packed f16x2 MUFU: deltas -> half2 -> ex2 -> P frags ----
        uint32_t pl[8], ph[8];
#pragma unroll
        for (int nt = 0; nt < 8; nt++) {
            pl[nt] = ex2_h2(h2pack(sacc[nt][0] - Klo, sacc[nt][1] - Klo));
            ph[nt] = ex2_h2(h2pack(sacc[nt][2] - Khi, sacc[nt][3] - Khi));
        }

        // rescale O/l only when some row's max moved (exact skip otherwise)
        const bool need = (corr_lo != 1.0f) || (corr_hi != 1.0f);
        if (__any_sync(0xffffffffu, need)) {
#pragma unroll
            for (int nt = 0; nt < 9; nt++) {
                oacc[nt][0] *= corr_lo;
                oacc[nt][1] *= corr_lo;
                oacc[nt][2] *= corr_hi;
                oacc[nt][3] *= corr_hi;
            }
        }

        // ---- O += P @ V ; l += P @ 1 ----
#pragma unroll
        for (int kk = 0; kk < 4; kk++) {
            uint32_t pa[4];
            pa[0] = pl[2 * kk];
            pa[1] = ph[2 * kk];
            pa[2] = pl[2 * kk + 1];
            pa[3] = ph[2 * kk + 1];
            uint32_t vb[4][4];
#pragma unroll
            for (int np = 0; np < 4; np++) {
                const int row = kk * 16 + l15;
                const int col = np * 16 + hi16;
                ldm_x4t(vb[np], Vsmb + (uint32_t)(row * LDV + col) * 2);
            }
#pragma unroll
            for (int nt = 0; nt < 8; nt++) {
                const int np = nt >> 1, o = (nt & 1) * 2;
                mma_f16(oacc[nt], pa, vb[np][o], vb[np][o + 1]);
            }
            mma_f16(oacc[8], pa, ONESH2, ONESH2);   // row sums of P
        }
    }

    // epilogue: O /= l
    float inv_lo = 1.0f / oacc[8][0];
    float inv_hi = 1.0f / oacc[8][2];
    __half* Ob = g_O + ((size_t)(b * TT + q0 + w * 16)) * DD + h * HD;
#pragma unroll
    for (int nt = 0; nt < 8; nt++) {
        *(uint32_t*)(Ob + (size_t)(gr)     * DD + nt * 8 + gq * 2) =
            h2pack(oacc[nt][0] * inv_lo, oacc[nt][1] * inv_lo);
        *(uint32_t*)(Ob + (size_t)(gr + 8) * DD + nt * 8 + gq * 2) =
            h2pack(oacc[nt][2] * inv_hi, oacc[nt][3] * inv_hi);
    }
}

// ---------------------------------------------------------------------------
extern "C" void kernel_launch(void* const* d_in, const int* in_sizes, int n_in,
                              void* d_out, int out_size)
{
    const float* query = (const float*)d_in[0];
    const float* key_  = (const float*)d_in[1];
    const float* value = (const float*)d_in[2];
    const float* Wq    = (const float*)d_in[3];
    const float* bq    = (const float*)d_in[4];
    const float* Wk    = (const float*)d_in[5];
    const float* bk    = (const float*)d_in[6];
    const float* Wv    = (const float*)d_in[7];
    const float* bv    = (const float*)d_in[8];
    const float* Wo    = (const float*)d_in[9];
    const float* bo    = (const float*)d_in[10];
    float* out = (float*)d_out;

    static int attr_done = 0;
    if (!attr_done) {
        cudaFuncSetAttribute(qkv_kernel, cudaFuncAttributeMaxDynamicSharedMemorySize,
                             GEMM_SMEM_BYTES);
        cudaFuncSetAttribute(out_kernel, cudaFuncAttributeMaxDynamicSharedMemorySize,
                             GEMM_SMEM_BYTES);
        cudaFuncSetAttribute(attn_kernel, cudaFuncAttributeMaxDynamicSharedMemorySize,
                             ATTN_SMEM_BYTES);
        attr_done = 1;
    }

    round_all<<<(XPAIRS + WPAIRS) / 256, 256>>>(
        (const float4*)query, (const float4*)key_, (const float4*)value,
        (const float4*)Wq, (const float4*)Wk, (const float4*)Wv, (const float4*)Wo);

    dim3 gqkv(MROWS / 128, DD / 128, 3);
    qkv_kernel<<<gqkv, 256, GEMM_SMEM_BYTES>>>(bq, bk, bv);

    dim3 gattn(TT / 64, HH, BB);
    attn_kernel<<<gattn, 128, ATTN_SMEM_BYTES>>>();

    dim3 gout(MROWS / 128, DD / 128);
    out_kernel<<<gout, 256, GEMM_SMEM_BYTES>>>(bo, out);
}